// round 3
// baseline (speedup 1.0000x reference)
#include <cuda_runtime.h>
#include <cstdint>
#include <cstddef>

#define DEV static __device__ __forceinline__
typedef unsigned long long u64;

constexpr int Bb = 16, Ll = 8192;
constexpr int CH = 8;                 // L-chunks in phase 1
constexpr int NSUB = (Ll / CH) / 128; // 8 subtiles of 128 per chunk
constexpr float SCALE = 0.08838834764831845f; // 1/sqrt(128)

// ---------------- scratch (device globals; no allocation) ----------------
__device__ float g_VT[(size_t)Bb * Ll * 128];     // V transposed: [b][l][v]
__device__ float g_kvpart[Bb * CH * 128 * 128];   // kv partials
__device__ float g_kspart[Bb * CH * 128];         // ksum partials
__device__ float g_kv[Bb * 128 * 128];            // kv final: [b][m][v]
__device__ float g_ksum[Bb * 128];                // ksum final

// ---------------- packed f32x2 helpers ----------------
DEV u64 pk2(float lo, float hi) { u64 r; asm("mov.b64 %0,{%1,%2};" : "=l"(r) : "f"(lo), "f"(hi)); return r; }
DEV float2 upk2(u64 v) { float2 r; asm("mov.b64 {%0,%1},%2;" : "=f"(r.x), "=f"(r.y) : "l"(v)); return r; }
DEV void fma2(u64 &d, u64 a, u64 b) { asm("fma.rn.f32x2 %0,%1,%2,%0;" : "+l"(d) : "l"(a), "l"(b)); }
DEV float rcp_nr(float x) { float r; asm("rcp.approx.f32 %0,%1;" : "=f"(r) : "f"(x)); return r * (2.0f - x * r); }

// ---------------- cp.async helpers ----------------
DEV void cp16(uint32_t s, const void *g) { asm volatile("cp.async.ca.shared.global [%0],[%1],16;" :: "r"(s), "l"(g)); }
DEV void cpcommit() { asm volatile("cp.async.commit_group;"); }
DEV void cpwait() { asm volatile("cp.async.wait_group 0;"); }

// Load a 128x128 fp32 tile (row-major, row stride gstride floats) into smem
// with a permuted 16B-unit layout: 16B chunk c4 of a row goes to unit
// ((c4&1)<<4)|(c4>>1). Fragment reads then touch 16 consecutive units ->
// all 8 bank quads -> 4-phase (minimum) conflict-free LDS.128.
DEV void load_tile(uint32_t sb, const float *g, int gstride) {
    int t = threadIdx.x, c4 = t & 31, r0 = t >> 5;
    uint32_t ub = (uint32_t)((((c4 & 1) << 4) | (c4 >> 1)) * 16); // unit byte offset
#pragma unroll
    for (int i = 0; i < 16; i++) {
        int row = i * 8 + r0;
        cp16(sb + (uint32_t)row * 512u + ub, g + (size_t)row * gstride + c4 * 4);
    }
}

// ---------------- 128x128x128 SIMT GEMM core (8x8 microtile, f32x2) ----------
// C[8ty+i][8tx+{2j,2j+1}] += sum_r A[r][8ty+i] * B[r][8tx+...]
// A-frag: units ty, 16+ty (2 distinct/warp -> broadcast); B-frag: units tx, 16+tx.
template <bool KSUM, bool DEN>
DEV void mm128(const float4 *A4, const float4 *B4, int ty, int tx,
               u64 (*c)[4], float *ksum, const float *ksv, u64 *dnm) {
#pragma unroll 4
    for (int r = 0; r < 128; r++) {
        float4 a0 = A4[r * 32 + ty], a1 = A4[r * 32 + 16 + ty];
        float4 b0 = B4[r * 32 + tx], b1 = B4[r * 32 + 16 + tx];
        u64 bp0 = pk2(b0.x, b0.y), bp1 = pk2(b0.z, b0.w);
        u64 bp2 = pk2(b1.x, b1.y), bp3 = pk2(b1.z, b1.w);
        float av[8] = {a0.x, a0.y, a0.z, a0.w, a1.x, a1.y, a1.z, a1.w};
#pragma unroll
        for (int i = 0; i < 8; i++) {
            u64 ad = pk2(av[i], av[i]);
            fma2(c[i][0], ad, bp0); fma2(c[i][1], ad, bp1);
            fma2(c[i][2], ad, bp2); fma2(c[i][3], ad, bp3);
            if (KSUM) ksum[i] += av[i];
        }
        if (DEN) {
            u64 kd = pk2(ksv[r], ksv[r]);
            fma2(dnm[0], kd, bp0); fma2(dnm[1], kd, bp1);
            fma2(dnm[2], kd, bp2); fma2(dnm[3], kd, bp3);
        }
    }
}

// ---------------- Kernel T: V[b][v][l] -> VT[b][l][v] ----------------
__global__ __launch_bounds__(256, 1) void k_trans(const float *__restrict__ V) {
    extern __shared__ float ts[]; // 16384 floats, XOR-swizzled: word(v,l)=v*128+(l^(v>>2))
    int b = blockIdx.y, l0 = blockIdx.x * 128, t = threadIdx.x;
    int c4 = t & 31, r0 = t >> 5;
#pragma unroll
    for (int i = 0; i < 16; i++) {
        int v = i * 8 + r0, lb = c4 * 4;
        float4 g = *(const float4 *)(V + ((size_t)(b * 128 + v)) * Ll + l0 + lb);
        int s = v >> 2;
        ts[v * 128 + ((lb + 0) ^ s)] = g.x;
        ts[v * 128 + ((lb + 1) ^ s)] = g.y;
        ts[v * 128 + ((lb + 2) ^ s)] = g.z;
        ts[v * 128 + ((lb + 3) ^ s)] = g.w;
    }
    __syncthreads();
#pragma unroll
    for (int i = 0; i < 16; i++) {
        int l = i * 8 + r0, vb = (t & 31) * 4;
        float4 o; // (vb+k)>>2 == c4 for k<4 -> same xor as writes; reads conflict-free
        o.x = ts[(vb + 0) * 128 + (l ^ c4)];
        o.y = ts[(vb + 1) * 128 + (l ^ c4)];
        o.z = ts[(vb + 2) * 128 + (l ^ c4)];
        o.w = ts[(vb + 3) * 128 + (l ^ c4)];
        *(float4 *)(g_VT + ((size_t)b * Ll + l0 + l) * 128 + vb) = o;
    }
}

// ---------------- Kernel P1: phi_k + kv/ksum partials ----------------
__global__ __launch_bounds__(256, 1) void k_p1(const float *__restrict__ keys,
                                               const float *__restrict__ feats) {
    extern __shared__ float smem[];
    uint32_t sb = (uint32_t)__cvta_generic_to_shared(smem);
    const float4 *W4 = (const float4 *)smem;
    const float4 *Bf4 = (const float4 *)(smem + 16384);
    const float4 *Ph4 = (const float4 *)(smem + 32768);
    float4 *PhW = (float4 *)(smem + 32768);
    int b = blockIdx.y, ch = blockIdx.x, t = threadIdx.x;
    int ty = t >> 4, tx = t & 15;

    load_tile(sb, feats, 128); // W[d][m], natural layout
    cpcommit();

    u64 c2[8][4]; float ksm[8];
#pragma unroll
    for (int i = 0; i < 8; i++) {
        ksm[i] = 0.f;
#pragma unroll
        for (int j = 0; j < 4; j++) c2[i][j] = 0ull;
    }

    for (int st = 0; st < NSUB; st++) {
        int l0 = ch * (Ll / CH) + st * 128;
        __syncthreads(); // previous GEMM2 done with buf
        load_tile(sb + 65536, keys + (size_t)b * 128 * Ll + l0, Ll); // K[d][l]
        cpcommit(); cpwait(); __syncthreads();

        u64 p[8][4];
#pragma unroll
        for (int i = 0; i < 8; i++)
#pragma unroll
            for (int j = 0; j < 4; j++) p[i][j] = 0ull;

        // GEMM1: phi[l][m] = relu(K^T W)*s : A = K tile (ty = l), B = W (tx = m)
        mm128<false, false>(Bf4, W4, ty, tx, p, nullptr, nullptr, nullptr);

#pragma unroll
        for (int i = 0; i < 8; i++) {
            float v[8];
#pragma unroll
            for (int j = 0; j < 4; j++) {
                float2 f = upk2(p[i][j]);
                v[2 * j] = fmaxf(f.x * SCALE, 0.f);
                v[2 * j + 1] = fmaxf(f.y * SCALE, 0.f);
            }
            int row = ty * 8 + i; // l-local
            PhW[row * 32 + tx] = make_float4(v[0], v[1], v[2], v[3]);
            PhW[row * 32 + 16 + tx] = make_float4(v[4], v[5], v[6], v[7]);
        }
        __syncthreads(); // phi written; K reads done -> buf reusable
        load_tile(sb + 65536, g_VT + ((size_t)b * Ll + l0) * 128, 128); // VT[l][v]
        cpcommit(); cpwait(); __syncthreads();

        // GEMM2: kv[m][v] += phi^T ... A = phi[l][m-frag] (ty=m), B = VT[l][v-frag] (tx=v)
        mm128<true, false>(Ph4, Bf4, ty, tx, c2, ksm, nullptr, nullptr);
    }

    float *kvp = g_kvpart + (size_t)(b * CH + ch) * 16384;
#pragma unroll
    for (int i = 0; i < 8; i++) {
        float2 f0 = upk2(c2[i][0]), f1 = upk2(c2[i][1]);
        float2 f2 = upk2(c2[i][2]), f3 = upk2(c2[i][3]);
        float4 *dst = (float4 *)(kvp + (ty * 8 + i) * 128 + tx * 8);
        dst[0] = make_float4(f0.x, f0.y, f1.x, f1.y);
        dst[1] = make_float4(f2.x, f2.y, f3.x, f3.y);
    }
    if (tx == 0) {
#pragma unroll
        for (int i = 0; i < 8; i++)
            g_kspart[(b * CH + ch) * 128 + ty * 8 + i] = ksm[i];
    }
}

// ---------------- Kernel R: reduce partials ----------------
__global__ __launch_bounds__(256) void k_red() {
    int b = blockIdx.x >> 4, sl = blockIdx.x & 15, t = threadIdx.x;
    int e = sl * 1024 + t * 4;
    float4 acc = make_float4(0.f, 0.f, 0.f, 0.f);
#pragma unroll
    for (int ch = 0; ch < CH; ch++) {
        float4 v = *(const float4 *)(g_kvpart + (size_t)(b * CH + ch) * 16384 + e);
        acc.x += v.x; acc.y += v.y; acc.z += v.z; acc.w += v.w;
    }
    *(float4 *)(g_kv + (size_t)b * 16384 + e) = acc;
    if (sl == 0 && t < 128) {
        float s = 0.f;
#pragma unroll
        for (int ch = 0; ch < CH; ch++) s += g_kspart[(b * CH + ch) * 128 + t];
        g_ksum[b * 128 + t] = s;
    }
}

// ---------------- Kernel P2: phi_q + out ----------------
__global__ __launch_bounds__(256, 1) void k_p2(const float *__restrict__ queries,
                                               const float *__restrict__ feats,
                                               float *__restrict__ out) {
    extern __shared__ float smem[];
    uint32_t sb = (uint32_t)__cvta_generic_to_shared(smem);
    const float4 *W4 = (const float4 *)smem;
    const float4 *Bf4 = (const float4 *)(smem + 16384);
    const float4 *Ph4 = (const float4 *)(smem + 32768);
    float4 *PhW = (float4 *)(smem + 32768);
    const float *Ks = smem + 49152;
    int b = blockIdx.y, l0 = blockIdx.x * 128, t = threadIdx.x;
    int ty = t >> 4, tx = t & 15;

    load_tile(sb, feats, 128);
    load_tile(sb + 65536, queries + (size_t)b * 128 * Ll + l0, Ll);
    cpcommit(); cpwait(); __syncthreads();

    u64 p[8][4];
#pragma unroll
    for (int i = 0; i < 8; i++)
#pragma unroll
        for (int j = 0; j < 4; j++) p[i][j] = 0ull;

    // GEMM1: phi_q[m][l] : A = W (ty = m), B = Q tile (tx = l)
    mm128<false, false>(W4, Bf4, ty, tx, p, nullptr, nullptr, nullptr);

#pragma unroll
    for (int i = 0; i < 8; i++) {
        float v[8];
#pragma unroll
        for (int j = 0; j < 4; j++) {
            float2 f = upk2(p[i][j]);
            v[2 * j] = fmaxf(f.x * SCALE, 0.f);
            v[2 * j + 1] = fmaxf(f.y * SCALE, 0.f);
        }
        int row = ty * 8 + i; // m
        PhW[row * 32 + tx] = make_float4(v[0], v[1], v[2], v[3]);
        PhW[row * 32 + 16 + tx] = make_float4(v[4], v[5], v[6], v[7]);
    }
    __syncthreads();
    load_tile(sb + 65536, g_kv + (size_t)b * 16384, 128); // kv[m][v]
    if (t < 32) cp16(sb + 196608 + (uint32_t)t * 16, g_ksum + b * 128 + t * 4);
    cpcommit(); cpwait(); __syncthreads();

    u64 c2[8][4], dnm[4];
#pragma unroll
    for (int j = 0; j < 4; j++) dnm[j] = 0ull;
#pragma unroll
    for (int i = 0; i < 8; i++)
#pragma unroll
        for (int j = 0; j < 4; j++) c2[i][j] = 0ull;

    // GEMM2: out[v][l] = sum_m kv[m][v]*phi_q[m][l]; denom folded via ksum
    mm128<false, true>(Bf4, Ph4, ty, tx, c2, nullptr, Ks, dnm);

    float rl[8];
#pragma unroll
    for (int j = 0; j < 4; j++) {
        float2 d = upk2(dnm[j]);
        rl[2 * j] = rcp_nr(d.x);
        rl[2 * j + 1] = rcp_nr(d.y);
    }
#pragma unroll
    for (int i = 0; i < 8; i++) {
        float2 f0 = upk2(c2[i][0]), f1 = upk2(c2[i][1]);
        float2 f2 = upk2(c2[i][2]), f3 = upk2(c2[i][3]);
        float4 *dst = (float4 *)(out + ((size_t)(b * 128 + ty * 8 + i)) * Ll + l0 + tx * 8);
        dst[0] = make_float4(f0.x * rl[0], f0.y * rl[1], f1.x * rl[2], f1.y * rl[3]);
        dst[1] = make_float4(f2.x * rl[4], f2.y * rl[5], f3.x * rl[6], f3.y * rl[7]);
    }
}

// ---------------- launch ----------------
extern "C" void kernel_launch(void *const *d_in, const int *in_sizes, int n_in,
                              void *d_out, int out_size) {
    (void)in_sizes; (void)n_in; (void)out_size;
    const float *keys = (const float *)d_in[0];
    const float *values = (const float *)d_in[1];
    const float *queries = (const float *)d_in[2];
    const float *feats = (const float *)d_in[3];
    float *out = (float *)d_out;

    cudaFuncSetAttribute(k_trans, cudaFuncAttributeMaxDynamicSharedMemorySize, 65536);
    cudaFuncSetAttribute(k_p1, cudaFuncAttributeMaxDynamicSharedMemorySize, 197120);
    cudaFuncSetAttribute(k_p2, cudaFuncAttributeMaxDynamicSharedMemorySize, 197120);

    dim3 gt(Ll / 128, Bb);
    k_trans<<<gt, 256, 65536>>>(values);
    dim3 g1(CH, Bb);
    k_p1<<<g1, 256, 197120>>>(keys, feats);
    k_red<<<256, 256>>>();
    dim3 g2(Ll / 128, Bb);
    k_p2<<<g2, 256, 197120>>>(queries, feats, out);
}